// round 2
// baseline (speedup 1.0000x reference)
#include <cuda_runtime.h>
#include <math_constants.h>

#define BB 4
#define HH 512
#define WW 512
#define HW (HH*WW)
#define NKPT 512
#define CAP 65536
#define NFEAT 128

#define TILE 64
#define HALO 15
#define LDIM (TILE + 2*HALO)   // 94
#define SP   96                // padded smem row stride
#define NPIX (LDIM*LDIM)
#define NMS_SMEM (LDIM*SP*4*2 + LDIM*SP*2)   // 2 float bufs + 2 uchar bufs

// Output layout (float32, reference tuple order)
#define OFF_SCORE 0
#define OFF_KPTS  (BB*HW)
#define OFF_FEAS  (OFF_KPTS + BB*NKPT*4)
#define OFF_PIX   (OFF_FEAS + BB*NFEAT*NKPT)

// Scratch
__device__ unsigned long long g_cand[BB*CAP];
__device__ unsigned char g_cmask[BB*HW];
__device__ int g_count[BB];
__device__ int g_thr[BB];
__device__ int g_sel[BB*NKPT];

__global__ void k_init() {
    if (threadIdx.x < BB) g_count[threadIdx.x] = 0;
}

// Fully fused: score gating + simple_nms (init pool + 2 iterations) + output
// score2d + candidate compaction. One block per 64x64 output tile.
__global__ void k_nms(const float* __restrict__ bev,
                      const float* __restrict__ raw,
                      float* __restrict__ out) {
    extern __shared__ unsigned char smraw[];
    float* s   = (float*)smraw;                 // score tile (with halo)
    float* tmp = s + LDIM*SP;                   // h-pass intermediate
    unsigned char* mk  = (unsigned char*)(tmp + LDIM*SP);  // max_mask
    unsigned char* sup = mk + LDIM*SP;                      // supp_mask

    const int b   = blockIdx.z;
    const int gx0 = blockIdx.x * TILE - HALO;
    const int gy0 = blockIdx.y * TILE - HALO;
    const float* g2 = bev + (b*7 + 2)*HW;
    const float* rw = raw + b*HW;

    // Load gated score with -inf outside the image (exact reduce_window pad)
    for (int idx = threadIdx.x; idx < NPIX; idx += blockDim.x) {
        int ly = idx / LDIM, lx = idx - ly*LDIM;
        int gy = gy0 + ly, gx = gx0 + lx;
        float v = -CUDART_INF_F;
        if ((unsigned)gy < HH && (unsigned)gx < WW) {
            int g = gy*WW + gx;
            v = rw[g] * (g2[g] > 0.f ? 1.f : 0.f);
        }
        s[ly*SP + lx] = v;
    }
    __syncthreads();

    // --- initial max_mask: 7x7 maxpool (separable) ---
    for (int idx = threadIdx.x; idx < NPIX; idx += blockDim.x) {
        int ly = idx / LDIM, lx = idx - ly*LDIM;
        int x0 = max(lx-3, 0), x1 = min(lx+3, LDIM-1);
        float m = -CUDART_INF_F;
        for (int x = x0; x <= x1; ++x) m = fmaxf(m, s[ly*SP + x]);
        tmp[ly*SP + lx] = m;
    }
    __syncthreads();
    for (int idx = threadIdx.x; idx < NPIX; idx += blockDim.x) {
        int ly = idx / LDIM, lx = idx - ly*LDIM;
        int y0 = max(ly-3, 0), y1 = min(ly+3, LDIM-1);
        float m = -CUDART_INF_F;
        for (int y = y0; y <= y1; ++y) m = fmaxf(m, tmp[y*SP + lx]);
        mk[ly*SP + lx] = (m == s[ly*SP + lx]) ? 1 : 0;
    }
    __syncthreads();

    // --- 2 suppression iterations ---
    for (int it = 0; it < 2; ++it) {
        // h-dilate mask -> tmp (as float 0/1)
        for (int idx = threadIdx.x; idx < NPIX; idx += blockDim.x) {
            int ly = idx / LDIM, lx = idx - ly*LDIM;
            int x0 = max(lx-3, 0), x1 = min(lx+3, LDIM-1);
            unsigned char m = 0;
            for (int x = x0; x <= x1; ++x) m |= mk[ly*SP + x];
            tmp[ly*SP + lx] = m ? 1.f : 0.f;
        }
        __syncthreads();
        // v-dilate -> sup
        for (int idx = threadIdx.x; idx < NPIX; idx += blockDim.x) {
            int ly = idx / LDIM, lx = idx - ly*LDIM;
            int y0 = max(ly-3, 0), y1 = min(ly+3, LDIM-1);
            float m = 0.f;
            for (int y = y0; y <= y1; ++y) m = fmaxf(m, tmp[y*SP + lx]);
            sup[ly*SP + lx] = (m > 0.f) ? 1 : 0;
        }
        __syncthreads();
        // h-pool of supp_scores (sup ? 0 : s) -> tmp
        for (int idx = threadIdx.x; idx < NPIX; idx += blockDim.x) {
            int ly = idx / LDIM, lx = idx - ly*LDIM;
            int x0 = max(lx-3, 0), x1 = min(lx+3, LDIM-1);
            float m = -CUDART_INF_F;
            for (int x = x0; x <= x1; ++x) {
                float v = sup[ly*SP + x] ? 0.f : s[ly*SP + x];
                m = fmaxf(m, v);
            }
            tmp[ly*SP + lx] = m;
        }
        __syncthreads();
        // v-pool + mask update: mask |= (pool==supp_score) & ~supp
        for (int idx = threadIdx.x; idx < NPIX; idx += blockDim.x) {
            int ly = idx / LDIM, lx = idx - ly*LDIM;
            int y0 = max(ly-3, 0), y1 = min(ly+3, LDIM-1);
            float m = -CUDART_INF_F;
            for (int y = y0; y <= y1; ++y) m = fmaxf(m, tmp[y*SP + lx]);
            int p = ly*SP + lx;
            if (!sup[p]) {
                float sv = s[p];
                if (m == sv) mk[p] = 1;
            }
        }
        __syncthreads();
    }

    // --- emit: score2d output + candidate compaction (inner tile only) ---
    for (int idx = threadIdx.x; idx < TILE*TILE; idx += blockDim.x) {
        int ty = idx / TILE, tx = idx - ty*TILE;
        int ly = ty + HALO,  lx = tx + HALO;
        int gy = blockIdx.y*TILE + ty, gx = blockIdx.x*TILE + tx;
        int g = gy*WW + gx;
        float sv = s[ly*SP + lx];
        out[OFF_SCORE + b*HW + g] = sv;
        unsigned char c = (mk[ly*SP + lx] && sv > 0.f) ? 1 : 0;
        g_cmask[b*HW + g] = c;
        if (c) {
            int pos = atomicAdd(&g_count[b], 1);
            if (pos < CAP) {
                unsigned long long key =
                    ((unsigned long long)__float_as_uint(sv) << 32) |
                    (unsigned int)(HW - 1 - g);
                g_cand[b*CAP + pos] = key;
            }
        }
    }
}

// 512-bin histogram on score bits >> 21; suffix-scan to find threshold bin
// guaranteeing >= min(n, NKPT) survivors.
__global__ void k_hist() {
    __shared__ unsigned int h[512];
    int b = blockIdx.x;
    int n = min(g_count[b], CAP);
    for (int i = threadIdx.x; i < 512; i += blockDim.x) h[i] = 0;
    __syncthreads();
    for (int i = threadIdx.x; i < n; i += blockDim.x) {
        unsigned int sb = (unsigned int)(g_cand[b*CAP + i] >> 32);
        atomicAdd(&h[sb >> 21], 1u);
    }
    __syncthreads();
    // suffix sum (Hillis-Steele)
    for (int off = 1; off < 512; off <<= 1) {
        unsigned int v = 0;
        if (threadIdx.x < 512)
            v = h[threadIdx.x] +
                ((threadIdx.x + off < 512) ? h[threadIdx.x + off] : 0u);
        __syncthreads();
        if (threadIdx.x < 512) h[threadIdx.x] = v;
        __syncthreads();
    }
    unsigned int target = (unsigned int)min(n, NKPT);
    if (target == 0) {
        if (threadIdx.x == 0) g_thr[b] = 0;
    } else if (threadIdx.x < 512) {
        bool ge   = h[threadIdx.x] >= target;
        bool next = (threadIdx.x + 1 < 512) ? (h[threadIdx.x + 1] >= target)
                                            : false;
        if (ge && !next) g_thr[b] = threadIdx.x;
    }
}

// Exact rank for survivors only: rank = # keys strictly greater (over ALL n).
// Key ordering reproduces lax.top_k tie-breaking exactly.
__global__ void k_rank() {
    int b = blockIdx.y;
    int n = min(g_count[b], CAP);
    int wpb = blockDim.x >> 5;
    if (blockIdx.x * wpb >= n) return;
    int cid = blockIdx.x * wpb + (threadIdx.x >> 5);
    if (cid >= n) return;
    const unsigned long long* base = g_cand + b*CAP;
    unsigned long long key = base[cid];
    if ((unsigned int)(key >> 53) < (unsigned int)g_thr[b]) return;
    int lane = threadIdx.x & 31;
    int rank = 0;
    for (int j = lane; j < n; j += 32) rank += (base[j] > key) ? 1 : 0;
    #pragma unroll
    for (int off = 16; off; off >>= 1)
        rank += __shfl_down_sync(0xffffffffu, rank, off);
    if (lane == 0 && rank < NKPT)
        g_sel[b*NKPT + rank] = HW - 1 - (int)(key & 0xffffffffu);
}

// cold fallback: fewer than NKPT candidates -> -1 fillers, ascending index
__global__ void k_fill() {
    int b = blockIdx.x;
    int n = g_count[b];
    if (n >= NKPT) return;
    if (n > CAP) n = CAP;
    int slot = n;
    for (int p = 0; p < HW && slot < NKPT; ++p)
        if (!g_cmask[b*HW + p]) g_sel[b*NKPT + (slot++)] = p;
}

// all gathers in one launch: feats + kpts + pixels
__global__ void k_gather(const float* __restrict__ bev,
                         const float* __restrict__ feat,
                         float* __restrict__ out) {
    int t = blockIdx.x * blockDim.x + threadIdx.x;
    if (t < BB*NKPT) {
        int b = t / NKPT;
        int idx = g_sel[t];
        int u = idx / WW, v = idx - u*WW;
        float* ok = out + OFF_KPTS + t*4;
        ok[0] = bev[(b*7 + 3)*HW + idx];
        ok[1] = bev[(b*7 + 4)*HW + idx];
        ok[2] = 0.f;
        ok[3] = 1.f;
        float* op = out + OFF_PIX + t*2;
        op[0] = (float)u;
        op[1] = (float)v;
    }
    if (t >= BB*NFEAT*NKPT) return;
    int k  = t % NKPT;
    int bc = t / NKPT;
    int b  = bc / NFEAT;
    out[OFF_FEAS + t] = feat[bc*HW + g_sel[b*NKPT + k]];
}

extern "C" void kernel_launch(void* const* d_in, const int* in_sizes, int n_in,
                              void* d_out, int out_size) {
    const float* bev  = (const float*)d_in[0];
    const float* raw  = (const float*)d_in[1];
    const float* feat = (const float*)d_in[2];
    float* out = (float*)d_out;

    static bool attr_set = false;
    if (!attr_set) {
        cudaFuncSetAttribute(k_nms, cudaFuncAttributeMaxDynamicSharedMemorySize,
                             NMS_SMEM);
        attr_set = true;
    }

    k_init<<<1, 32>>>();

    dim3 ngrid(WW/TILE, HH/TILE, BB);   // 8 x 8 x 4
    k_nms<<<ngrid, 256, NMS_SMEM>>>(bev, raw, out);

    k_hist<<<BB, 512>>>();

    dim3 rgrid((CAP + 7) / 8, BB);      // 8 warps per 256-thread block
    k_rank<<<rgrid, 256>>>();

    k_fill<<<BB, 1>>>();

    const int TB = 256;
    k_gather<<<(BB*NFEAT*NKPT + TB - 1)/TB, TB>>>(bev, feat, out);
}